// round 1
// baseline (speedup 1.0000x reference)
#include <cuda_runtime.h>
#include <cstdint>

#define BB       8
#define NN       8192
#define NPOINT   1024
#define NSAMPLE  32
#define CFEAT    64
#define CIN0     67      // 3 + 64

// ------------------------------------------------------------------
// scratch (no allocations allowed) : ball-query group indices
// ------------------------------------------------------------------
__device__ int g_gidx[BB * NPOINT * NSAMPLE];

// ==================================================================
// Kernel 1: furthest point sampling. One block per batch.
// 512 threads, 16 points per thread held in registers; xyz mirrored
// in dynamic shared memory for broadcasting the selected point.
// Distance arithmetic matches the reference exactly (no FMA
// contraction, left-to-right adds, fminf), argmax = first max index.
// Writes new_xyz directly into d_out (first 8*1024*3 floats).
// ==================================================================
#define FPS_T 512
#define FPS_P (NN / FPS_T)   // 16

__global__ void __launch_bounds__(FPS_T, 1)
fps_kernel(const float* __restrict__ xyz, float* __restrict__ newxyz)
{
    extern __shared__ float sm[];
    float* sx = sm;
    float* sy = sm + NN;
    float* sz = sm + 2 * NN;
    float* wv = sm + 3 * NN;           // 16 warp-partial values
    int*   wi = (int*)(wv + 16);       // 16 warp-partial indices
    float* qs = (float*)(wi + 16);     // 3 broadcast coords

    const int b = blockIdx.x;
    const float* bx = xyz + (size_t)b * NN * 3;
    float* out = newxyz + (size_t)b * NPOINT * 3;
    const int t = threadIdx.x;

    float px[FPS_P], py[FPS_P], pz[FPS_P], mind[FPS_P];
#pragma unroll
    for (int j = 0; j < FPS_P; j++) {
        int i = t * FPS_P + j;
        float x = bx[i * 3 + 0];
        float y = bx[i * 3 + 1];
        float z = bx[i * 3 + 2];
        px[j] = x; py[j] = y; pz[j] = z;
        sx[i] = x; sy[i] = y; sz[i] = z;
        mind[j] = 1e10f;
    }
    __syncthreads();

    float qx = sx[0], qy = sy[0], qz = sz[0];
    if (t == 0) { out[0] = qx; out[1] = qy; out[2] = qz; }

    const int lane = t & 31;
    const int warp = t >> 5;

    for (int it = 1; it < NPOINT; it++) {
        float bv = -1.0f;
        int   bi = 0x7fffffff;
#pragma unroll
        for (int j = 0; j < FPS_P; j++) {
            float dx = __fsub_rn(px[j], qx);
            float dy = __fsub_rn(py[j], qy);
            float dz = __fsub_rn(pz[j], qz);
            float d  = __fadd_rn(__fadd_rn(__fmul_rn(dx, dx), __fmul_rn(dy, dy)),
                                 __fmul_rn(dz, dz));
            float m  = fminf(mind[j], d);
            mind[j] = m;
            if (m > bv) { bv = m; bi = t * FPS_P + j; }   // strict > keeps lowest j
        }
        // warp argmax (first-index tiebreak)
#pragma unroll
        for (int off = 16; off > 0; off >>= 1) {
            float ov = __shfl_xor_sync(0xffffffffu, bv, off);
            int   oi = __shfl_xor_sync(0xffffffffu, bi, off);
            if (ov > bv || (ov == bv && oi < bi)) { bv = ov; bi = oi; }
        }
        if (lane == 0) { wv[warp] = bv; wi[warp] = bi; }
        __syncthreads();
        if (t < 32) {
            bv = (t < FPS_T / 32) ? wv[t] : -1.0f;
            bi = (t < FPS_T / 32) ? wi[t] : 0x7fffffff;
#pragma unroll
            for (int off = 16; off > 0; off >>= 1) {
                float ov = __shfl_xor_sync(0xffffffffu, bv, off);
                int   oi = __shfl_xor_sync(0xffffffffu, bi, off);
                if (ov > bv || (ov == bv && oi < bi)) { bv = ov; bi = oi; }
            }
            if (t == 0) {
                float nx = sx[bi], ny = sy[bi], nz = sz[bi];
                qs[0] = nx; qs[1] = ny; qs[2] = nz;
                out[it * 3 + 0] = nx;
                out[it * 3 + 1] = ny;
                out[it * 3 + 2] = nz;
            }
        }
        __syncthreads();
        qx = qs[0]; qy = qs[1]; qz = qs[2];
    }
}

// ==================================================================
// Kernel 2: ball query. One warp per center; scans points in index
// order in chunks of 32 using ballot/popc slot assignment, early
// exit once 32 found (~1K points expected). Pads with the first
// in-radius index (which always exists: the center itself).
// ==================================================================
__global__ void __launch_bounds__(256)
ballquery_kernel(const float* __restrict__ xyz, const float* __restrict__ newxyz)
{
    const int gw   = (blockIdx.x * blockDim.x + threadIdx.x) >> 5;
    const int lane = threadIdx.x & 31;
    if (gw >= BB * NPOINT) return;
    const int b = gw >> 10;
    const float* bx = xyz + (size_t)b * NN * 3;
    const float cx = newxyz[gw * 3 + 0];
    const float cy = newxyz[gw * 3 + 1];
    const float cz = newxyz[gw * 3 + 2];
    int* out = g_gidx + gw * NSAMPLE;
    const float R2 = (float)0.04;   // f32(cast of double 0.2*0.2) — matches jax constant

    int cnt = 0, firstIdx = 0;
    for (int base = 0; base < NN; base += 32) {
        const int i = base + lane;
        float dx = __fsub_rn(bx[i * 3 + 0], cx);
        float dy = __fsub_rn(bx[i * 3 + 1], cy);
        float dz = __fsub_rn(bx[i * 3 + 2], cz);
        float d  = __fadd_rn(__fadd_rn(__fmul_rn(dx, dx), __fmul_rn(dy, dy)),
                             __fmul_rn(dz, dz));
        bool in = d < R2;
        unsigned mask = __ballot_sync(0xffffffffu, in);
        if (mask) {
            if (cnt == 0) firstIdx = base + (__ffs(mask) - 1);
            if (in) {
                int slot = cnt + __popc(mask & ((1u << lane) - 1u));
                if (slot < NSAMPLE) out[slot] = i;
            }
            cnt += __popc(mask);
            if (cnt >= NSAMPLE) break;
        }
    }
    if (lane >= cnt) out[lane] = (cnt > 0) ? firstIdx : 0;
}

// ==================================================================
// Kernel 3: gather + 3-layer pointwise MLP + maxpool.
// 256 threads, 8 groups per block; weights (transposed [c][o]) live
// in shared memory, loaded once per block. Thread (n = lane, p =
// warp) computes 8 output channels per sample for layers 0/1 and 16
// for layer 2, float4 weight broadcasts from SMEM, odd-pitch x/h
// buffers for conflict-free column reads.
// ==================================================================
#define MLP_T   256
#define NG      8
#define XPITCH  69
#define HPITCH  65
#define H3PITCH 129

__global__ void __launch_bounds__(MLP_T, 2)
mlp_kernel(const float* __restrict__ xyz, const float* __restrict__ feat,
           const float* __restrict__ w0, const float* __restrict__ s0g, const float* __restrict__ b0g,
           const float* __restrict__ w1, const float* __restrict__ s1g, const float* __restrict__ b1g,
           const float* __restrict__ w2, const float* __restrict__ s2g, const float* __restrict__ b2g,
           const float* __restrict__ newxyz, float* __restrict__ outfeat)
{
    extern __shared__ float sm[];
    float* w0s = sm;                    // 67*64
    float* w1s = w0s + CIN0 * 64;       // 64*64
    float* w2s = w1s + 64 * 64;         // 64*128
    float* sc0 = w2s + 64 * 128;
    float* bi0 = sc0 + 64;
    float* sc1 = bi0 + 64;
    float* bi1 = sc1 + 64;
    float* sc2 = bi1 + 64;              // 128
    float* bi2 = sc2 + 128;             // 128
    float* xb  = bi2 + 128;             // 32*69
    float* h1  = xb + 32 * XPITCH;      // 32*65
    float* h2  = h1 + 32 * HPITCH;      // 32*65
    float* h3  = h2 + 32 * HPITCH;      // 32*129

    const int t = threadIdx.x;
    const int n = t & 31;   // sample in group
    const int p = t >> 5;   // warp = output-channel slice

    for (int i = t; i < CIN0 * 64; i += MLP_T) { int o = i & 63,  c = i >> 6; w0s[i] = w0[o * CIN0 + c]; }
    for (int i = t; i < 64 * 64;  i += MLP_T) { int o = i & 63,  c = i >> 6; w1s[i] = w1[o * 64 + c]; }
    for (int i = t; i < 64 * 128; i += MLP_T) { int o = i & 127, c = i >> 7; w2s[i] = w2[o * 64 + c]; }
    if (t < 64)  { sc0[t] = s0g[t]; bi0[t] = b0g[t]; sc1[t] = s1g[t]; bi1[t] = b1g[t]; }
    if (t < 128) { sc2[t] = s2g[t]; bi2[t] = b2g[t]; }
    __syncthreads();

    for (int g = 0; g < NG; g++) {
        const int gi = blockIdx.x * NG + g;
        const int b  = gi >> 10;
        const int s  = gi & 1023;
        const int pi = g_gidx[gi * NSAMPLE + n];
        const float cx = newxyz[gi * 3 + 0];
        const float cy = newxyz[gi * 3 + 1];
        const float cz = newxyz[gi * 3 + 2];

        // gather: x[n][0:3] = xyz[pi]-center, x[n][3:67] = features[pi]
        const float* frow = feat + ((size_t)b * NN + pi) * CFEAT;
        float4 f0 = *(const float4*)(frow + p * 8);
        float4 f1 = *(const float4*)(frow + p * 8 + 4);
        float* xr = xb + n * XPITCH;
        if (p == 0) {
            const float* prow = xyz + ((size_t)b * NN + pi) * 3;
            xr[0] = __fsub_rn(prow[0], cx);
            xr[1] = __fsub_rn(prow[1], cy);
            xr[2] = __fsub_rn(prow[2], cz);
        }
        {
            float* xd = xr + 3 + p * 8;
            xd[0] = f0.x; xd[1] = f0.y; xd[2] = f0.z; xd[3] = f0.w;
            xd[4] = f1.x; xd[5] = f1.y; xd[6] = f1.z; xd[7] = f1.w;
        }
        __syncthreads();

        // ---- layer 0: 67 -> 64 ----
        {
            float acc[8];
#pragma unroll
            for (int j = 0; j < 8; j++) acc[j] = 0.0f;
            const int ob = p * 8;
            for (int c = 0; c < CIN0; c++) {
                float xv = xb[n * XPITCH + c];
                const float4* wr = (const float4*)(w0s + c * 64 + ob);
                float4 wa = wr[0], wb = wr[1];
                acc[0] = fmaf(xv, wa.x, acc[0]);
                acc[1] = fmaf(xv, wa.y, acc[1]);
                acc[2] = fmaf(xv, wa.z, acc[2]);
                acc[3] = fmaf(xv, wa.w, acc[3]);
                acc[4] = fmaf(xv, wb.x, acc[4]);
                acc[5] = fmaf(xv, wb.y, acc[5]);
                acc[6] = fmaf(xv, wb.z, acc[6]);
                acc[7] = fmaf(xv, wb.w, acc[7]);
            }
#pragma unroll
            for (int j = 0; j < 8; j++) {
                float v = __fadd_rn(__fmul_rn(acc[j], sc0[ob + j]), bi0[ob + j]);
                h1[n * HPITCH + ob + j] = fmaxf(v, 0.0f);
            }
        }
        __syncthreads();

        // ---- layer 1: 64 -> 64 ----
        {
            float acc[8];
#pragma unroll
            for (int j = 0; j < 8; j++) acc[j] = 0.0f;
            const int ob = p * 8;
            for (int c = 0; c < 64; c++) {
                float xv = h1[n * HPITCH + c];
                const float4* wr = (const float4*)(w1s + c * 64 + ob);
                float4 wa = wr[0], wb = wr[1];
                acc[0] = fmaf(xv, wa.x, acc[0]);
                acc[1] = fmaf(xv, wa.y, acc[1]);
                acc[2] = fmaf(xv, wa.z, acc[2]);
                acc[3] = fmaf(xv, wa.w, acc[3]);
                acc[4] = fmaf(xv, wb.x, acc[4]);
                acc[5] = fmaf(xv, wb.y, acc[5]);
                acc[6] = fmaf(xv, wb.z, acc[6]);
                acc[7] = fmaf(xv, wb.w, acc[7]);
            }
#pragma unroll
            for (int j = 0; j < 8; j++) {
                float v = __fadd_rn(__fmul_rn(acc[j], sc1[ob + j]), bi1[ob + j]);
                h2[n * HPITCH + ob + j] = fmaxf(v, 0.0f);
            }
        }
        __syncthreads();

        // ---- layer 2: 64 -> 128 ----
        {
            float acc[16];
#pragma unroll
            for (int j = 0; j < 16; j++) acc[j] = 0.0f;
            const int ob = p * 16;
            for (int c = 0; c < 64; c++) {
                float xv = h2[n * HPITCH + c];
                const float4* wr = (const float4*)(w2s + c * 128 + ob);
#pragma unroll
                for (int q = 0; q < 4; q++) {
                    float4 w4 = wr[q];
                    acc[q * 4 + 0] = fmaf(xv, w4.x, acc[q * 4 + 0]);
                    acc[q * 4 + 1] = fmaf(xv, w4.y, acc[q * 4 + 1]);
                    acc[q * 4 + 2] = fmaf(xv, w4.z, acc[q * 4 + 2]);
                    acc[q * 4 + 3] = fmaf(xv, w4.w, acc[q * 4 + 3]);
                }
            }
#pragma unroll
            for (int j = 0; j < 16; j++) {
                float v = __fadd_rn(__fmul_rn(acc[j], sc2[ob + j]), bi2[ob + j]);
                h3[n * H3PITCH + ob + j] = fmaxf(v, 0.0f);
            }
        }
        __syncthreads();

        // ---- maxpool over 32 samples, write transposed (B,128,S) ----
        if (t < 128) {
            float m = h3[t];
#pragma unroll 4
            for (int k = 1; k < 32; k++) m = fmaxf(m, h3[k * H3PITCH + t]);
            outfeat[((size_t)b * 128 + t) * NPOINT + s] = m;
        }
        __syncthreads();
    }
}

// ==================================================================
// launch
// ==================================================================
extern "C" void kernel_launch(void* const* d_in, const int* in_sizes, int n_in,
                              void* d_out, int out_size)
{
    (void)in_sizes; (void)n_in; (void)out_size;
    const float* xyz  = (const float*)d_in[0];
    const float* feat = (const float*)d_in[1];
    const float* w0 = (const float*)d_in[2];
    const float* s0 = (const float*)d_in[3];
    const float* b0 = (const float*)d_in[4];
    const float* w1 = (const float*)d_in[5];
    const float* s1 = (const float*)d_in[6];
    const float* b1 = (const float*)d_in[7];
    const float* w2 = (const float*)d_in[8];
    const float* s2 = (const float*)d_in[9];
    const float* b2 = (const float*)d_in[10];

    float* out     = (float*)d_out;
    float* newxyz  = out;                       // (B, NPOINT, 3)
    float* outfeat = out + (size_t)BB * NPOINT * 3;  // (B, 128, NPOINT)

    const int FPS_SMEM = (3 * NN + 16 + 16 + 4) * 4;   // 98448 B
    const int MLP_SMEM = 27584 * 4;                    // 110336 B
    cudaFuncSetAttribute(fps_kernel, cudaFuncAttributeMaxDynamicSharedMemorySize, FPS_SMEM);
    cudaFuncSetAttribute(mlp_kernel, cudaFuncAttributeMaxDynamicSharedMemorySize, MLP_SMEM);

    fps_kernel<<<BB, FPS_T, FPS_SMEM>>>(xyz, newxyz);
    ballquery_kernel<<<(BB * NPOINT * 32) / 256, 256>>>(xyz, newxyz);
    mlp_kernel<<<BB * NPOINT / NG, MLP_T, MLP_SMEM>>>(
        xyz, feat, w0, s0, b0, w1, s1, b1, w2, s2, b2, newxyz, outfeat);
}

// round 2
// speedup vs baseline: 1.3630x; 1.3630x over previous
#include <cuda_runtime.h>
#include <cstdint>

#define BB       8
#define NN       8192
#define NPOINT   1024
#define NSAMPLE  32
#define CFEAT    64
#define CIN0     67      // 3 + 64

// ------------------------------------------------------------------
// scratch (no allocations allowed) : ball-query group indices
// ------------------------------------------------------------------
__device__ int g_gidx[BB * NPOINT * NSAMPLE];

// ------------------------------------------------------------------
// packed f32x2 helpers (Blackwell sm_103a)
// ------------------------------------------------------------------
__device__ __forceinline__ unsigned long long pk2(float lo, float hi) {
    unsigned long long r;
    asm("mov.b64 %0, {%1, %2};" : "=l"(r) : "f"(lo), "f"(hi));
    return r;
}
__device__ __forceinline__ void upk2(unsigned long long v, float& lo, float& hi) {
    asm("mov.b64 {%0, %1}, %2;" : "=f"(lo), "=f"(hi) : "l"(v));
}
__device__ __forceinline__ unsigned long long add2_(unsigned long long a, unsigned long long b) {
    unsigned long long r;
    asm("add.rn.f32x2 %0, %1, %2;" : "=l"(r) : "l"(a), "l"(b));
    return r;
}
__device__ __forceinline__ unsigned long long mul2_(unsigned long long a, unsigned long long b) {
    unsigned long long r;
    asm("mul.rn.f32x2 %0, %1, %2;" : "=l"(r) : "l"(a), "l"(b));
    return r;
}
__device__ __forceinline__ unsigned long long fma2_(unsigned long long a, unsigned long long b,
                                                    unsigned long long c) {
    unsigned long long r;
    asm("fma.rn.f32x2 %0, %1, %2, %3;" : "=l"(r) : "l"(a), "l"(b), "l"(c));
    return r;
}

// ==================================================================
// Kernel 1: furthest point sampling. One block per batch.
// 512 threads x 16 points in registers (packed f32x2 pairs).
// Per iter: packed distance + scalar fminf/fmaxf (value-only max),
// REDUX warp reductions, deferred first-index equality scan.
// Arithmetic matches reference bit-exactly:
//   dx = px + (-qx)  ==  px - qx  (IEEE exact)
//   d  = (dx*dx + dy*dy) + dz*dz  (rn, no fma contraction; f32x2 is
//        per-lane identical to scalar rn ops)
//   argmax = min index where mind == exact max   (first-max index)
// ==================================================================
#define FPS_T 512
#define FPS_P (NN / FPS_T)   // 16

__global__ void __launch_bounds__(FPS_T, 1)
fps_kernel(const float* __restrict__ xyz, float* __restrict__ newxyz)
{
    extern __shared__ float sm[];
    float* sx = sm;
    float* sy = sm + NN;
    float* sz = sm + 2 * NN;
    unsigned* wv = (unsigned*)(sm + 3 * NN);   // 16 warp value partials
    unsigned* wi = wv + 16;                    // 16 warp index partials

    const int b = blockIdx.x;
    const float* bx = xyz + (size_t)b * NN * 3;
    float* out = newxyz + (size_t)b * NPOINT * 3;
    const int t = threadIdx.x;
    const int lane = t & 31;
    const int warp = t >> 5;

    unsigned long long px2[FPS_P / 2], py2[FPS_P / 2], pz2[FPS_P / 2];
    float mind[FPS_P];
#pragma unroll
    for (int k = 0; k < FPS_P / 2; k++) {
        int i0 = t * FPS_P + 2 * k;
        int i1 = i0 + 1;
        float x0 = bx[i0 * 3 + 0], y0 = bx[i0 * 3 + 1], z0 = bx[i0 * 3 + 2];
        float x1 = bx[i1 * 3 + 0], y1 = bx[i1 * 3 + 1], z1 = bx[i1 * 3 + 2];
        px2[k] = pk2(x0, x1); py2[k] = pk2(y0, y1); pz2[k] = pk2(z0, z1);
        sx[i0] = x0; sy[i0] = y0; sz[i0] = z0;
        sx[i1] = x1; sy[i1] = y1; sz[i1] = z1;
        mind[2 * k] = 1e10f; mind[2 * k + 1] = 1e10f;
    }
    __syncthreads();

    float qx = sx[0], qy = sy[0], qz = sz[0];
    if (t == 0) { out[0] = qx; out[1] = qy; out[2] = qz; }

    for (int it = 1; it < NPOINT; it++) {
        const unsigned long long nqx = pk2(-qx, -qx);
        const unsigned long long nqy = pk2(-qy, -qy);
        const unsigned long long nqz = pk2(-qz, -qz);
        float vloc = -1.0f;
#pragma unroll
        for (int k = 0; k < FPS_P / 2; k++) {
            unsigned long long dx = add2_(px2[k], nqx);
            unsigned long long dy = add2_(py2[k], nqy);
            unsigned long long dz = add2_(pz2[k], nqz);
            unsigned long long d2 = add2_(add2_(mul2_(dx, dx), mul2_(dy, dy)),
                                          mul2_(dz, dz));
            float d0, d1;
            upk2(d2, d0, d1);
            float m0 = fminf(mind[2 * k], d0);
            float m1 = fminf(mind[2 * k + 1], d1);
            mind[2 * k] = m0;
            mind[2 * k + 1] = m1;
            vloc = fmaxf(vloc, fmaxf(m0, m1));
        }
        // block max value (distances >= 0, so uint order == float order)
        unsigned vb = __reduce_max_sync(0xffffffffu, __float_as_uint(vloc));
        if (lane == 0) wv[warp] = vb;
        __syncthreads();
        float vmaxf = __uint_as_float(__reduce_max_sync(0xffffffffu, wv[lane & 15]));

        // first (lowest) index whose mind equals the max
        int idxl = 0x7fffffff;
#pragma unroll
        for (int j = FPS_P - 1; j >= 0; j--)
            if (mind[j] == vmaxf) idxl = t * FPS_P + j;
        unsigned wm = __reduce_min_sync(0xffffffffu, (unsigned)idxl);
        if (lane == 0) wi[warp] = wm;
        __syncthreads();
        unsigned bi = __reduce_min_sync(0xffffffffu, wi[lane & 15]);

        qx = sx[bi]; qy = sy[bi]; qz = sz[bi];
        if (t == 0) {
            out[it * 3 + 0] = qx;
            out[it * 3 + 1] = qy;
            out[it * 3 + 2] = qz;
        }
    }
}

// ==================================================================
// Kernel 2: ball query. One warp per center; index-order scan in
// chunks of 32 with ballot/popc slot assignment, early exit.
// ==================================================================
__global__ void __launch_bounds__(256)
ballquery_kernel(const float* __restrict__ xyz, const float* __restrict__ newxyz)
{
    const int gw   = (blockIdx.x * blockDim.x + threadIdx.x) >> 5;
    const int lane = threadIdx.x & 31;
    if (gw >= BB * NPOINT) return;
    const int b = gw >> 10;
    const float* bx = xyz + (size_t)b * NN * 3;
    const float cx = newxyz[gw * 3 + 0];
    const float cy = newxyz[gw * 3 + 1];
    const float cz = newxyz[gw * 3 + 2];
    int* out = g_gidx + gw * NSAMPLE;
    const float R2 = (float)0.04;

    int cnt = 0, firstIdx = 0;
    for (int base = 0; base < NN; base += 32) {
        const int i = base + lane;
        float dx = __fsub_rn(bx[i * 3 + 0], cx);
        float dy = __fsub_rn(bx[i * 3 + 1], cy);
        float dz = __fsub_rn(bx[i * 3 + 2], cz);
        float d  = __fadd_rn(__fadd_rn(__fmul_rn(dx, dx), __fmul_rn(dy, dy)),
                             __fmul_rn(dz, dz));
        bool in = d < R2;
        unsigned mask = __ballot_sync(0xffffffffu, in);
        if (mask) {
            if (cnt == 0) firstIdx = base + (__ffs(mask) - 1);
            if (in) {
                int slot = cnt + __popc(mask & ((1u << lane) - 1u));
                if (slot < NSAMPLE) out[slot] = i;
            }
            cnt += __popc(mask);
            if (cnt >= NSAMPLE) break;
        }
    }
    if (lane >= cnt) out[lane] = (cnt > 0) ? firstIdx : 0;
}

// ==================================================================
// Kernel 3: gather + 3-layer pointwise MLP + maxpool, packed f32x2
// FMA (2 channels per instruction; identical per-channel
// accumulation order -> bit-identical results to scalar version).
// ==================================================================
#define MLP_T   256
#define NG      8
#define XPITCH  69
#define HPITCH  65
#define H3PITCH 129

__global__ void __launch_bounds__(MLP_T, 2)
mlp_kernel(const float* __restrict__ xyz, const float* __restrict__ feat,
           const float* __restrict__ w0, const float* __restrict__ s0g, const float* __restrict__ b0g,
           const float* __restrict__ w1, const float* __restrict__ s1g, const float* __restrict__ b1g,
           const float* __restrict__ w2, const float* __restrict__ s2g, const float* __restrict__ b2g,
           const float* __restrict__ newxyz, float* __restrict__ outfeat)
{
    extern __shared__ float sm[];
    float* w0s = sm;                    // 67*64
    float* w1s = w0s + CIN0 * 64;       // 64*64
    float* w2s = w1s + 64 * 64;         // 64*128
    float* sc0 = w2s + 64 * 128;
    float* bi0 = sc0 + 64;
    float* sc1 = bi0 + 64;
    float* bi1 = sc1 + 64;
    float* sc2 = bi1 + 64;              // 128
    float* bi2 = sc2 + 128;             // 128
    float* xb  = bi2 + 128;             // 32*69
    float* h1  = xb + 32 * XPITCH;      // 32*65
    float* h2  = h1 + 32 * HPITCH;      // 32*65
    float* h3  = h2 + 32 * HPITCH;      // 32*129

    const int t = threadIdx.x;
    const int n = t & 31;   // sample in group
    const int p = t >> 5;   // warp = output-channel slice

    for (int i = t; i < CIN0 * 64; i += MLP_T) { int o = i & 63,  c = i >> 6; w0s[i] = w0[o * CIN0 + c]; }
    for (int i = t; i < 64 * 64;  i += MLP_T) { int o = i & 63,  c = i >> 6; w1s[i] = w1[o * 64 + c]; }
    for (int i = t; i < 64 * 128; i += MLP_T) { int o = i & 127, c = i >> 7; w2s[i] = w2[o * 64 + c]; }
    if (t < 64)  { sc0[t] = s0g[t]; bi0[t] = b0g[t]; sc1[t] = s1g[t]; bi1[t] = b1g[t]; }
    if (t < 128) { sc2[t] = s2g[t]; bi2[t] = b2g[t]; }
    __syncthreads();

    for (int g = 0; g < NG; g++) {
        const int gi = blockIdx.x * NG + g;
        const int b  = gi >> 10;
        const int s  = gi & 1023;
        const int pi = g_gidx[gi * NSAMPLE + n];
        const float cx = newxyz[gi * 3 + 0];
        const float cy = newxyz[gi * 3 + 1];
        const float cz = newxyz[gi * 3 + 2];

        // gather: x[n][0:3] = xyz[pi]-center, x[n][3:67] = features[pi]
        const float* frow = feat + ((size_t)b * NN + pi) * CFEAT;
        float4 f0 = *(const float4*)(frow + p * 8);
        float4 f1 = *(const float4*)(frow + p * 8 + 4);
        float* xr = xb + n * XPITCH;
        if (p == 0) {
            const float* prow = xyz + ((size_t)b * NN + pi) * 3;
            xr[0] = __fsub_rn(prow[0], cx);
            xr[1] = __fsub_rn(prow[1], cy);
            xr[2] = __fsub_rn(prow[2], cz);
        }
        {
            float* xd = xr + 3 + p * 8;
            xd[0] = f0.x; xd[1] = f0.y; xd[2] = f0.z; xd[3] = f0.w;
            xd[4] = f1.x; xd[5] = f1.y; xd[6] = f1.z; xd[7] = f1.w;
        }
        __syncthreads();

        // ---- layer 0: 67 -> 64 (8 channels/thread, packed pairs) ----
        {
            unsigned long long acc[4] = {0ull, 0ull, 0ull, 0ull};
            const int ob = p * 8;
            for (int c = 0; c < CIN0; c++) {
                float xv = xb[n * XPITCH + c];
                unsigned long long xv2 = pk2(xv, xv);
                const ulonglong2* wr = (const ulonglong2*)(w0s + c * 64 + ob);
                ulonglong2 wa = wr[0], wb = wr[1];
                acc[0] = fma2_(xv2, wa.x, acc[0]);
                acc[1] = fma2_(xv2, wa.y, acc[1]);
                acc[2] = fma2_(xv2, wb.x, acc[2]);
                acc[3] = fma2_(xv2, wb.y, acc[3]);
            }
#pragma unroll
            for (int q = 0; q < 4; q++) {
                float a0, a1;
                upk2(acc[q], a0, a1);
                int o0 = ob + 2 * q;
                float v0 = __fadd_rn(__fmul_rn(a0, sc0[o0]),     bi0[o0]);
                float v1 = __fadd_rn(__fmul_rn(a1, sc0[o0 + 1]), bi0[o0 + 1]);
                h1[n * HPITCH + o0]     = fmaxf(v0, 0.0f);
                h1[n * HPITCH + o0 + 1] = fmaxf(v1, 0.0f);
            }
        }
        __syncthreads();

        // ---- layer 1: 64 -> 64 ----
        {
            unsigned long long acc[4] = {0ull, 0ull, 0ull, 0ull};
            const int ob = p * 8;
            for (int c = 0; c < 64; c++) {
                float xv = h1[n * HPITCH + c];
                unsigned long long xv2 = pk2(xv, xv);
                const ulonglong2* wr = (const ulonglong2*)(w1s + c * 64 + ob);
                ulonglong2 wa = wr[0], wb = wr[1];
                acc[0] = fma2_(xv2, wa.x, acc[0]);
                acc[1] = fma2_(xv2, wa.y, acc[1]);
                acc[2] = fma2_(xv2, wb.x, acc[2]);
                acc[3] = fma2_(xv2, wb.y, acc[3]);
            }
#pragma unroll
            for (int q = 0; q < 4; q++) {
                float a0, a1;
                upk2(acc[q], a0, a1);
                int o0 = ob + 2 * q;
                float v0 = __fadd_rn(__fmul_rn(a0, sc1[o0]),     bi1[o0]);
                float v1 = __fadd_rn(__fmul_rn(a1, sc1[o0 + 1]), bi1[o0 + 1]);
                h2[n * HPITCH + o0]     = fmaxf(v0, 0.0f);
                h2[n * HPITCH + o0 + 1] = fmaxf(v1, 0.0f);
            }
        }
        __syncthreads();

        // ---- layer 2: 64 -> 128 (16 channels/thread) ----
        {
            unsigned long long acc[8] = {0ull, 0ull, 0ull, 0ull, 0ull, 0ull, 0ull, 0ull};
            const int ob = p * 16;
            for (int c = 0; c < 64; c++) {
                float xv = h2[n * HPITCH + c];
                unsigned long long xv2 = pk2(xv, xv);
                const ulonglong2* wr = (const ulonglong2*)(w2s + c * 128 + ob);
                ulonglong2 wa = wr[0], wb = wr[1], wc = wr[2], wd = wr[3];
                acc[0] = fma2_(xv2, wa.x, acc[0]);
                acc[1] = fma2_(xv2, wa.y, acc[1]);
                acc[2] = fma2_(xv2, wb.x, acc[2]);
                acc[3] = fma2_(xv2, wb.y, acc[3]);
                acc[4] = fma2_(xv2, wc.x, acc[4]);
                acc[5] = fma2_(xv2, wc.y, acc[5]);
                acc[6] = fma2_(xv2, wd.x, acc[6]);
                acc[7] = fma2_(xv2, wd.y, acc[7]);
            }
#pragma unroll
            for (int q = 0; q < 8; q++) {
                float a0, a1;
                upk2(acc[q], a0, a1);
                int o0 = ob + 2 * q;
                float v0 = __fadd_rn(__fmul_rn(a0, sc2[o0]),     bi2[o0]);
                float v1 = __fadd_rn(__fmul_rn(a1, sc2[o0 + 1]), bi2[o0 + 1]);
                h3[n * H3PITCH + o0]     = fmaxf(v0, 0.0f);
                h3[n * H3PITCH + o0 + 1] = fmaxf(v1, 0.0f);
            }
        }
        __syncthreads();

        // ---- maxpool over 32 samples, write transposed (B,128,S) ----
        if (t < 128) {
            float m = h3[t];
#pragma unroll 4
            for (int k = 1; k < 32; k++) m = fmaxf(m, h3[k * H3PITCH + t]);
            outfeat[((size_t)b * 128 + t) * NPOINT + s] = m;
        }
        __syncthreads();
    }
}

// ==================================================================
// launch
// ==================================================================
extern "C" void kernel_launch(void* const* d_in, const int* in_sizes, int n_in,
                              void* d_out, int out_size)
{
    (void)in_sizes; (void)n_in; (void)out_size;
    const float* xyz  = (const float*)d_in[0];
    const float* feat = (const float*)d_in[1];
    const float* w0 = (const float*)d_in[2];
    const float* s0 = (const float*)d_in[3];
    const float* b0 = (const float*)d_in[4];
    const float* w1 = (const float*)d_in[5];
    const float* s1 = (const float*)d_in[6];
    const float* b1 = (const float*)d_in[7];
    const float* w2 = (const float*)d_in[8];
    const float* s2 = (const float*)d_in[9];
    const float* b2 = (const float*)d_in[10];

    float* out     = (float*)d_out;
    float* newxyz  = out;                            // (B, NPOINT, 3)
    float* outfeat = out + (size_t)BB * NPOINT * 3;  // (B, 128, NPOINT)

    const int FPS_SMEM = (3 * NN + 32) * 4 + 16;       // ~98464 B
    const int MLP_SMEM = 27584 * 4;                    // 110336 B
    cudaFuncSetAttribute(fps_kernel, cudaFuncAttributeMaxDynamicSharedMemorySize, FPS_SMEM);
    cudaFuncSetAttribute(mlp_kernel, cudaFuncAttributeMaxDynamicSharedMemorySize, MLP_SMEM);

    fps_kernel<<<BB, FPS_T, FPS_SMEM>>>(xyz, newxyz);
    ballquery_kernel<<<(BB * NPOINT * 32) / 256, 256>>>(xyz, newxyz);
    mlp_kernel<<<BB * NPOINT / NG, MLP_T, MLP_SMEM>>>(
        xyz, feat, w0, s0, b0, w1, s1, b1, w2, s2, b2, newxyz, outfeat);
}

// round 3
// speedup vs baseline: 1.3876x; 1.0180x over previous
#include <cuda_runtime.h>
#include <cstdint>

#define BB       8
#define NN       8192
#define NPOINT   1024
#define NSAMPLE  32
#define CFEAT    64
#define CIN0     67      // 3 + 64

// ------------------------------------------------------------------
// scratch (no allocations allowed) : ball-query group indices
// ------------------------------------------------------------------
__device__ int g_gidx[BB * NPOINT * NSAMPLE];

// ------------------------------------------------------------------
// packed f32x2 helpers (Blackwell sm_103a)
// ------------------------------------------------------------------
__device__ __forceinline__ unsigned long long pk2(float lo, float hi) {
    unsigned long long r;
    asm("mov.b64 %0, {%1, %2};" : "=l"(r) : "f"(lo), "f"(hi));
    return r;
}
__device__ __forceinline__ void upk2(unsigned long long v, float& lo, float& hi) {
    asm("mov.b64 {%0, %1}, %2;" : "=f"(lo), "=f"(hi) : "l"(v));
}
__device__ __forceinline__ unsigned long long add2_(unsigned long long a, unsigned long long b) {
    unsigned long long r;
    asm("add.rn.f32x2 %0, %1, %2;" : "=l"(r) : "l"(a), "l"(b));
    return r;
}
__device__ __forceinline__ unsigned long long mul2_(unsigned long long a, unsigned long long b) {
    unsigned long long r;
    asm("mul.rn.f32x2 %0, %1, %2;" : "=l"(r) : "l"(a), "l"(b));
    return r;
}
__device__ __forceinline__ unsigned long long fma2_(unsigned long long a, unsigned long long b,
                                                    unsigned long long c) {
    unsigned long long r;
    asm("fma.rn.f32x2 %0, %1, %2, %3;" : "=l"(r) : "l"(a), "l"(b), "l"(c));
    return r;
}

// ==================================================================
// Kernel 1: furthest point sampling. One block per batch.
// 512 threads x 16 points in registers (packed f32x2 pairs).
// SINGLE barrier per iteration:
//   per-warp: value max (REDUX) -> equality scan vs WARP max ->
//             first-index (REDUX min) -> lane0 stores (wmax, widx)
//   barrier
//   all warps redundantly combine the 16 (wmax, widx) pairs:
//             block max (REDUX) + min index among warps whose
//             wmax == block max (REDUX).
// Partial arrays are double-buffered by iteration parity (the single
// barrier otherwise allows a fast warp's next-iter store to race a
// slow warp's read).
// Arithmetic bit-matches the reference:
//   dx = px + (-qx); d = (dx*dx + dy*dy) + dz*dz   (rn, no fma)
//   argmax = first (lowest) index attaining the exact max
// ==================================================================
#define FPS_T 512
#define FPS_P (NN / FPS_T)   // 16

__global__ void __launch_bounds__(FPS_T, 1)
fps_kernel(const float* __restrict__ xyz, float* __restrict__ newxyz)
{
    extern __shared__ float sm[];
    float* sx = sm;
    float* sy = sm + NN;
    float* sz = sm + 2 * NN;
    unsigned* wv = (unsigned*)(sm + 3 * NN);   // [2][16] warp value partials
    unsigned* wi = wv + 32;                    // [2][16] warp index partials

    const int b = blockIdx.x;
    const float* bx = xyz + (size_t)b * NN * 3;
    float* out = newxyz + (size_t)b * NPOINT * 3;
    const int t = threadIdx.x;
    const int lane = t & 31;
    const int warp = t >> 5;

    unsigned long long px2[FPS_P / 2], py2[FPS_P / 2], pz2[FPS_P / 2];
    float mind[FPS_P];
#pragma unroll
    for (int k = 0; k < FPS_P / 2; k++) {
        int i0 = t * FPS_P + 2 * k;
        int i1 = i0 + 1;
        float x0 = bx[i0 * 3 + 0], y0 = bx[i0 * 3 + 1], z0 = bx[i0 * 3 + 2];
        float x1 = bx[i1 * 3 + 0], y1 = bx[i1 * 3 + 1], z1 = bx[i1 * 3 + 2];
        px2[k] = pk2(x0, x1); py2[k] = pk2(y0, y1); pz2[k] = pk2(z0, z1);
        sx[i0] = x0; sy[i0] = y0; sz[i0] = z0;
        sx[i1] = x1; sy[i1] = y1; sz[i1] = z1;
        mind[2 * k] = 1e10f; mind[2 * k + 1] = 1e10f;
    }
    __syncthreads();

    float qx = sx[0], qy = sy[0], qz = sz[0];
    if (t == 0) { out[0] = qx; out[1] = qy; out[2] = qz; }

    for (int it = 1; it < NPOINT; it++) {
        const unsigned long long nqx = pk2(-qx, -qx);
        const unsigned long long nqy = pk2(-qy, -qy);
        const unsigned long long nqz = pk2(-qz, -qz);
        float vloc = -1.0f;
#pragma unroll
        for (int k = 0; k < FPS_P / 2; k++) {
            unsigned long long dx = add2_(px2[k], nqx);
            unsigned long long dy = add2_(py2[k], nqy);
            unsigned long long dz = add2_(pz2[k], nqz);
            unsigned long long d2 = add2_(add2_(mul2_(dx, dx), mul2_(dy, dy)),
                                          mul2_(dz, dz));
            float d0, d1;
            upk2(d2, d0, d1);
            float m0 = fminf(mind[2 * k], d0);
            float m1 = fminf(mind[2 * k + 1], d1);
            mind[2 * k] = m0;
            mind[2 * k + 1] = m1;
            vloc = fmaxf(vloc, fmaxf(m0, m1));
        }
        // ---- pre-barrier, per-warp phase ----
        // warp max (all mind >= 0 so uint order == float order)
        unsigned wmax = __reduce_max_sync(0xffffffffu, __float_as_uint(vloc));
        float wmaxf = __uint_as_float(wmax);
        // first (lowest) local index whose mind equals the WARP max
        unsigned idxl = 0xffffffffu;
#pragma unroll
        for (int j = FPS_P - 1; j >= 0; j--)
            if (mind[j] == wmaxf) idxl = t * FPS_P + j;
        unsigned widx = __reduce_min_sync(0xffffffffu, idxl);

        const int par = (it & 1) << 4;      // double-buffer slot
        if (lane == 0) { wv[par + warp] = wmax; wi[par + warp] = widx; }
        __syncthreads();

        // ---- post-barrier combine (redundant across all warps) ----
        unsigned bvv = wv[par + (lane & 15)];
        unsigned bii = wi[par + (lane & 15)];
        unsigned vmax = __reduce_max_sync(0xffffffffu, bvv);
        unsigned bi   = __reduce_min_sync(0xffffffffu,
                                          (bvv == vmax) ? bii : 0xffffffffu);

        qx = sx[bi]; qy = sy[bi]; qz = sz[bi];
        if (t == 0) {
            out[it * 3 + 0] = qx;
            out[it * 3 + 1] = qy;
            out[it * 3 + 2] = qz;
        }
    }
}

// ==================================================================
// Kernel 2: ball query. One warp per center; index-order scan in
// chunks of 32 with ballot/popc slot assignment, early exit.
// ==================================================================
__global__ void __launch_bounds__(256)
ballquery_kernel(const float* __restrict__ xyz, const float* __restrict__ newxyz)
{
    const int gw   = (blockIdx.x * blockDim.x + threadIdx.x) >> 5;
    const int lane = threadIdx.x & 31;
    if (gw >= BB * NPOINT) return;
    const int b = gw >> 10;
    const float* bx = xyz + (size_t)b * NN * 3;
    const float cx = newxyz[gw * 3 + 0];
    const float cy = newxyz[gw * 3 + 1];
    const float cz = newxyz[gw * 3 + 2];
    int* out = g_gidx + gw * NSAMPLE;
    const float R2 = (float)0.04;

    int cnt = 0, firstIdx = 0;
    for (int base = 0; base < NN; base += 32) {
        const int i = base + lane;
        float dx = __fsub_rn(bx[i * 3 + 0], cx);
        float dy = __fsub_rn(bx[i * 3 + 1], cy);
        float dz = __fsub_rn(bx[i * 3 + 2], cz);
        float d  = __fadd_rn(__fadd_rn(__fmul_rn(dx, dx), __fmul_rn(dy, dy)),
                             __fmul_rn(dz, dz));
        bool in = d < R2;
        unsigned mask = __ballot_sync(0xffffffffu, in);
        if (mask) {
            if (cnt == 0) firstIdx = base + (__ffs(mask) - 1);
            if (in) {
                int slot = cnt + __popc(mask & ((1u << lane) - 1u));
                if (slot < NSAMPLE) out[slot] = i;
            }
            cnt += __popc(mask);
            if (cnt >= NSAMPLE) break;
        }
    }
    if (lane >= cnt) out[lane] = (cnt > 0) ? firstIdx : 0;
}

// ==================================================================
// Kernel 3: gather + 3-layer pointwise MLP + maxpool, packed f32x2
// FMA (2 channels per instruction; identical per-channel
// accumulation order -> bit-identical results to scalar version).
// ==================================================================
#define MLP_T   256
#define NG      8
#define XPITCH  69
#define HPITCH  65
#define H3PITCH 129

__global__ void __launch_bounds__(MLP_T, 2)
mlp_kernel(const float* __restrict__ xyz, const float* __restrict__ feat,
           const float* __restrict__ w0, const float* __restrict__ s0g, const float* __restrict__ b0g,
           const float* __restrict__ w1, const float* __restrict__ s1g, const float* __restrict__ b1g,
           const float* __restrict__ w2, const float* __restrict__ s2g, const float* __restrict__ b2g,
           const float* __restrict__ newxyz, float* __restrict__ outfeat)
{
    extern __shared__ float sm[];
    float* w0s = sm;                    // 67*64
    float* w1s = w0s + CIN0 * 64;       // 64*64
    float* w2s = w1s + 64 * 64;         // 64*128
    float* sc0 = w2s + 64 * 128;
    float* bi0 = sc0 + 64;
    float* sc1 = bi0 + 64;
    float* bi1 = sc1 + 64;
    float* sc2 = bi1 + 64;              // 128
    float* bi2 = sc2 + 128;             // 128
    float* xb  = bi2 + 128;             // 32*69
    float* h1  = xb + 32 * XPITCH;      // 32*65
    float* h2  = h1 + 32 * HPITCH;      // 32*65
    float* h3  = h2 + 32 * HPITCH;      // 32*129

    const int t = threadIdx.x;
    const int n = t & 31;   // sample in group
    const int p = t >> 5;   // warp = output-channel slice

    for (int i = t; i < CIN0 * 64; i += MLP_T) { int o = i & 63,  c = i >> 6; w0s[i] = w0[o * CIN0 + c]; }
    for (int i = t; i < 64 * 64;  i += MLP_T) { int o = i & 63,  c = i >> 6; w1s[i] = w1[o * 64 + c]; }
    for (int i = t; i < 64 * 128; i += MLP_T) { int o = i & 127, c = i >> 7; w2s[i] = w2[o * 64 + c]; }
    if (t < 64)  { sc0[t] = s0g[t]; bi0[t] = b0g[t]; sc1[t] = s1g[t]; bi1[t] = b1g[t]; }
    if (t < 128) { sc2[t] = s2g[t]; bi2[t] = b2g[t]; }
    __syncthreads();

    for (int g = 0; g < NG; g++) {
        const int gi = blockIdx.x * NG + g;
        const int b  = gi >> 10;
        const int s  = gi & 1023;
        const int pi = g_gidx[gi * NSAMPLE + n];
        const float cx = newxyz[gi * 3 + 0];
        const float cy = newxyz[gi * 3 + 1];
        const float cz = newxyz[gi * 3 + 2];

        // gather: x[n][0:3] = xyz[pi]-center, x[n][3:67] = features[pi]
        const float* frow = feat + ((size_t)b * NN + pi) * CFEAT;
        float4 f0 = *(const float4*)(frow + p * 8);
        float4 f1 = *(const float4*)(frow + p * 8 + 4);
        float* xr = xb + n * XPITCH;
        if (p == 0) {
            const float* prow = xyz + ((size_t)b * NN + pi) * 3;
            xr[0] = __fsub_rn(prow[0], cx);
            xr[1] = __fsub_rn(prow[1], cy);
            xr[2] = __fsub_rn(prow[2], cz);
        }
        {
            float* xd = xr + 3 + p * 8;
            xd[0] = f0.x; xd[1] = f0.y; xd[2] = f0.z; xd[3] = f0.w;
            xd[4] = f1.x; xd[5] = f1.y; xd[6] = f1.z; xd[7] = f1.w;
        }
        __syncthreads();

        // ---- layer 0: 67 -> 64 (8 channels/thread, packed pairs) ----
        {
            unsigned long long acc[4] = {0ull, 0ull, 0ull, 0ull};
            const int ob = p * 8;
#pragma unroll 4
            for (int c = 0; c < CIN0; c++) {
                float xv = xb[n * XPITCH + c];
                unsigned long long xv2 = pk2(xv, xv);
                const ulonglong2* wr = (const ulonglong2*)(w0s + c * 64 + ob);
                ulonglong2 wa = wr[0], wb = wr[1];
                acc[0] = fma2_(xv2, wa.x, acc[0]);
                acc[1] = fma2_(xv2, wa.y, acc[1]);
                acc[2] = fma2_(xv2, wb.x, acc[2]);
                acc[3] = fma2_(xv2, wb.y, acc[3]);
            }
#pragma unroll
            for (int q = 0; q < 4; q++) {
                float a0, a1;
                upk2(acc[q], a0, a1);
                int o0 = ob + 2 * q;
                float v0 = __fadd_rn(__fmul_rn(a0, sc0[o0]),     bi0[o0]);
                float v1 = __fadd_rn(__fmul_rn(a1, sc0[o0 + 1]), bi0[o0 + 1]);
                h1[n * HPITCH + o0]     = fmaxf(v0, 0.0f);
                h1[n * HPITCH + o0 + 1] = fmaxf(v1, 0.0f);
            }
        }
        __syncthreads();

        // ---- layer 1: 64 -> 64 ----
        {
            unsigned long long acc[4] = {0ull, 0ull, 0ull, 0ull};
            const int ob = p * 8;
#pragma unroll 4
            for (int c = 0; c < 64; c++) {
                float xv = h1[n * HPITCH + c];
                unsigned long long xv2 = pk2(xv, xv);
                const ulonglong2* wr = (const ulonglong2*)(w1s + c * 64 + ob);
                ulonglong2 wa = wr[0], wb = wr[1];
                acc[0] = fma2_(xv2, wa.x, acc[0]);
                acc[1] = fma2_(xv2, wa.y, acc[1]);
                acc[2] = fma2_(xv2, wb.x, acc[2]);
                acc[3] = fma2_(xv2, wb.y, acc[3]);
            }
#pragma unroll
            for (int q = 0; q < 4; q++) {
                float a0, a1;
                upk2(acc[q], a0, a1);
                int o0 = ob + 2 * q;
                float v0 = __fadd_rn(__fmul_rn(a0, sc1[o0]),     bi1[o0]);
                float v1 = __fadd_rn(__fmul_rn(a1, sc1[o0 + 1]), bi1[o0 + 1]);
                h2[n * HPITCH + o0]     = fmaxf(v0, 0.0f);
                h2[n * HPITCH + o0 + 1] = fmaxf(v1, 0.0f);
            }
        }
        __syncthreads();

        // ---- layer 2: 64 -> 128 (16 channels/thread) ----
        {
            unsigned long long acc[8] = {0ull, 0ull, 0ull, 0ull, 0ull, 0ull, 0ull, 0ull};
            const int ob = p * 16;
#pragma unroll 2
            for (int c = 0; c < 64; c++) {
                float xv = h2[n * HPITCH + c];
                unsigned long long xv2 = pk2(xv, xv);
                const ulonglong2* wr = (const ulonglong2*)(w2s + c * 128 + ob);
                ulonglong2 wa = wr[0], wb = wr[1], wc = wr[2], wd = wr[3];
                acc[0] = fma2_(xv2, wa.x, acc[0]);
                acc[1] = fma2_(xv2, wa.y, acc[1]);
                acc[2] = fma2_(xv2, wb.x, acc[2]);
                acc[3] = fma2_(xv2, wb.y, acc[3]);
                acc[4] = fma2_(xv2, wc.x, acc[4]);
                acc[5] = fma2_(xv2, wc.y, acc[5]);
                acc[6] = fma2_(xv2, wd.x, acc[6]);
                acc[7] = fma2_(xv2, wd.y, acc[7]);
            }
#pragma unroll
            for (int q = 0; q < 8; q++) {
                float a0, a1;
                upk2(acc[q], a0, a1);
                int o0 = ob + 2 * q;
                float v0 = __fadd_rn(__fmul_rn(a0, sc2[o0]),     bi2[o0]);
                float v1 = __fadd_rn(__fmul_rn(a1, sc2[o0 + 1]), bi2[o0 + 1]);
                h3[n * H3PITCH + o0]     = fmaxf(v0, 0.0f);
                h3[n * H3PITCH + o0 + 1] = fmaxf(v1, 0.0f);
            }
        }
        __syncthreads();

        // ---- maxpool over 32 samples, write transposed (B,128,S) ----
        if (t < 128) {
            float m = h3[t];
#pragma unroll 4
            for (int k = 1; k < 32; k++) m = fmaxf(m, h3[k * H3PITCH + t]);
            outfeat[((size_t)b * 128 + t) * NPOINT + s] = m;
        }
        __syncthreads();
    }
}

// ==================================================================
// launch
// ==================================================================
extern "C" void kernel_launch(void* const* d_in, const int* in_sizes, int n_in,
                              void* d_out, int out_size)
{
    (void)in_sizes; (void)n_in; (void)out_size;
    const float* xyz  = (const float*)d_in[0];
    const float* feat = (const float*)d_in[1];
    const float* w0 = (const float*)d_in[2];
    const float* s0 = (const float*)d_in[3];
    const float* b0 = (const float*)d_in[4];
    const float* w1 = (const float*)d_in[5];
    const float* s1 = (const float*)d_in[6];
    const float* b1 = (const float*)d_in[7];
    const float* w2 = (const float*)d_in[8];
    const float* s2 = (const float*)d_in[9];
    const float* b2 = (const float*)d_in[10];

    float* out     = (float*)d_out;
    float* newxyz  = out;                            // (B, NPOINT, 3)
    float* outfeat = out + (size_t)BB * NPOINT * 3;  // (B, 128, NPOINT)

    const int FPS_SMEM = (3 * NN + 64) * 4 + 16;       // ~98592 B
    const int MLP_SMEM = 27584 * 4;                    // 110336 B
    cudaFuncSetAttribute(fps_kernel, cudaFuncAttributeMaxDynamicSharedMemorySize, FPS_SMEM);
    cudaFuncSetAttribute(mlp_kernel, cudaFuncAttributeMaxDynamicSharedMemorySize, MLP_SMEM);

    fps_kernel<<<BB, FPS_T, FPS_SMEM>>>(xyz, newxyz);
    ballquery_kernel<<<(BB * NPOINT * 32) / 256, 256>>>(xyz, newxyz);
    mlp_kernel<<<BB * NPOINT / NG, MLP_T, MLP_SMEM>>>(
        xyz, feat, w0, s0, b0, w1, s1, b1, w2, s2, b2, newxyz, outfeat);
}